// round 6
// baseline (speedup 1.0000x reference)
#include <cuda_runtime.h>
#include <cuda_bf16.h>
#include <cstdint>

// Problem constants (shapes fixed by the reference)
#define NN      100000      // nodes
#define DIM     128         // feature dim (in == out)

// Scratch: __device__ globals (no cudaMalloc allowed).
// 16B-aligned: accessed via float4 stores and red.global.add.v4.f32.
__device__ __align__(16) float g_agg[(size_t)NN * DIM];
__device__ __align__(16) float g_cnt[NN];
__device__ int g_is64;   // 1 if edge_index buffer is int64, 0 if int32

// ---------------------------------------------------------------------------
// Kernel 0: detect edge_index element width.
// int64 little-endian values < 2^31 -> every odd int32 word is 0.
// Genuine int32 indices (uniform in [0,1e5)) are 0 at 8 sampled odd
// positions with prob ~1e-40.
// ---------------------------------------------------------------------------
__global__ void detect_kernel(const int* __restrict__ ei32) {
    int allzero = 1;
#pragma unroll
    for (int i = 1; i < 16; i += 2) allzero &= (ei32[i] == 0);
    g_is64 = allzero;
}

// ---------------------------------------------------------------------------
// Kernel 1: zero the scratch buffers (float4 stores, grid-stride)
// ---------------------------------------------------------------------------
__global__ void zero_kernel() {
    const size_t n4 = ((size_t)NN * DIM) / 4;
    float4 z = make_float4(0.f, 0.f, 0.f, 0.f);
    float4* a4 = reinterpret_cast<float4*>(g_agg);
    for (size_t i = (size_t)blockIdx.x * blockDim.x + threadIdx.x;
         i < n4; i += (size_t)gridDim.x * blockDim.x) {
        a4[i] = z;
    }
    for (size_t i = (size_t)blockIdx.x * blockDim.x + threadIdx.x;
         i < NN; i += (size_t)gridDim.x * blockDim.x) {
        g_cnt[i] = 0.f;
    }
}

// ---------------------------------------------------------------------------
// Kernel 2: edge scatter. One warp per edge.
//   Each lane: 1x float4 gather of x[src], 1x red.global.add.v4.f32 to agg[dst].
//   Lane 0: red.add.f32 on the degree counter.
// ---------------------------------------------------------------------------
__global__ void scatter_kernel(const float* __restrict__ x,
                               const void* __restrict__ ei,
                               int E) {
    int gtid = blockIdx.x * blockDim.x + threadIdx.x;
    int e    = gtid >> 5;
    int lane = gtid & 31;
    if (e >= E) return;

    long long src, dst;
    if (g_is64) {
        const long long* e64 = (const long long*)ei;
        src = e64[e];
        dst = e64[(size_t)E + e];
    } else {
        const int* e32 = (const int*)ei;
        src = e32[e];
        dst = e32[(size_t)E + e];
    }
    // Safety: never trap on a bad index (skip edge instead).
    if ((unsigned long long)src >= NN || (unsigned long long)dst >= NN) return;

    const float4* xs = reinterpret_cast<const float4*>(x + (size_t)src * DIM);
    float4 v = xs[lane];                 // coalesced 512B per warp, L2-resident

    float* dp = g_agg + (size_t)dst * DIM + lane * 4;
    asm volatile("red.global.add.v4.f32 [%0], {%1, %2, %3, %4};"
                 :: "l"(dp), "f"(v.x), "f"(v.y), "f"(v.z), "f"(v.w)
                 : "memory");

    if (lane == 0) {
        asm volatile("red.global.add.f32 [%0], %1;"
                     :: "l"(g_cnt + dst), "f"(1.0f)
                     : "memory");
    }
}

// ---------------------------------------------------------------------------
// Kernel 3: fused normalize + GEMM + bias.
//   out[i,:] = (agg[i,:]/max(cnt[i],1)) @ W_l + x[i,:] @ W_r + b_l
// Treated as [N,256] @ [256,128] with K chunked in 32s.
// Tile: 64 rows x 128 cols per block, 256 threads, 4x8 register blocking.
// ---------------------------------------------------------------------------
#define TILE_R  64
#define KCHUNK  32

__global__ __launch_bounds__(256, 2)
void gemm_kernel(const float* __restrict__ x,
                 const float* __restrict__ Wl,
                 const float* __restrict__ bl,
                 const float* __restrict__ Wr,
                 float* __restrict__ out,
                 int N) {
    __shared__ float Ash[TILE_R][KCHUNK + 1];  // +1 pad: kill bank conflicts
    __shared__ float Wsh[KCHUNK][DIM];
    __shared__ float inv_sh[TILE_R];

    const int tid = threadIdx.x;
    const int tx  = tid & 15;          // 16 col-groups of 8 cols
    const int ty  = tid >> 4;          // 16 row-groups of 4 rows
    const int row0 = blockIdx.x * TILE_R;

    // Per-row 1/max(cnt,1)
    if (tid < TILE_R) {
        int r = row0 + tid;
        float c = (r < N) ? g_cnt[r] : 1.0f;
        inv_sh[tid] = 1.0f / fmaxf(c, 1.0f);
    }
    __syncthreads();

    float acc[4][8];
#pragma unroll
    for (int r = 0; r < 4; r++)
#pragma unroll
        for (int c = 0; c < 8; c++) acc[r][c] = 0.f;

    // A-load mapping: row = tid/4, cols (tid%4)*8 .. +7  (2x float4)
    const int la_row = tid >> 2;
    const int la_col = (tid & 3) * 8;
    // W-load mapping: 32x128 chunk, each thread 4x float4.
    const int wf0 = tid * 4;

    for (int chunk = 0; chunk < 8; chunk++) {
        const bool is_agg = (chunk < 4);
        const int  kbase  = (is_agg ? chunk : chunk - 4) * KCHUNK;
        const float* src  = is_agg ? g_agg : x;
        const float* W    = is_agg ? Wl    : Wr;

        // ---- load A chunk (scaled if agg path) ----
        {
            int grow = row0 + la_row;
            float scale = is_agg ? inv_sh[la_row] : 1.0f;
            float4 v0, v1;
            if (grow < N) {
                const float4* p = reinterpret_cast<const float4*>(
                    src + (size_t)grow * DIM + kbase + la_col);
                v0 = p[0]; v1 = p[1];
            } else {
                v0 = v1 = make_float4(0.f, 0.f, 0.f, 0.f);
            }
            Ash[la_row][la_col + 0] = v0.x * scale;
            Ash[la_row][la_col + 1] = v0.y * scale;
            Ash[la_row][la_col + 2] = v0.z * scale;
            Ash[la_row][la_col + 3] = v0.w * scale;
            Ash[la_row][la_col + 4] = v1.x * scale;
            Ash[la_row][la_col + 5] = v1.y * scale;
            Ash[la_row][la_col + 6] = v1.z * scale;
            Ash[la_row][la_col + 7] = v1.w * scale;
        }
        // ---- load W chunk ----
#pragma unroll
        for (int j = 0; j < 4; j++) {
            int f    = wf0 + j;
            int krow = f >> 5;
            int kcol = (f & 31) * 4;
            const float4* p = reinterpret_cast<const float4*>(
                W + (size_t)(kbase + krow) * DIM + kcol);
            *reinterpret_cast<float4*>(&Wsh[krow][kcol]) = *p;
        }
        __syncthreads();

        // ---- compute ----
#pragma unroll
        for (int k = 0; k < KCHUNK; k++) {
            float a[4];
#pragma unroll
            for (int r = 0; r < 4; r++) a[r] = Ash[ty * 4 + r][k];
            float4 b0 = *reinterpret_cast<const float4*>(&Wsh[k][tx * 8]);
            float4 b1 = *reinterpret_cast<const float4*>(&Wsh[k][tx * 8 + 4]);
            const float bb[8] = {b0.x, b0.y, b0.z, b0.w, b1.x, b1.y, b1.z, b1.w};
#pragma unroll
            for (int r = 0; r < 4; r++)
#pragma unroll
                for (int c = 0; c < 8; c++)
                    acc[r][c] += a[r] * bb[c];
        }
        __syncthreads();
    }

    // ---- epilogue: bias + store (float4 x2 per row) ----
    float4 bias0 = *reinterpret_cast<const float4*>(bl + tx * 8);
    float4 bias1 = *reinterpret_cast<const float4*>(bl + tx * 8 + 4);
#pragma unroll
    for (int r = 0; r < 4; r++) {
        int grow = row0 + ty * 4 + r;
        if (grow < N) {
            float4 o0 = make_float4(acc[r][0] + bias0.x, acc[r][1] + bias0.y,
                                    acc[r][2] + bias0.z, acc[r][3] + bias0.w);
            float4 o1 = make_float4(acc[r][4] + bias1.x, acc[r][5] + bias1.y,
                                    acc[r][6] + bias1.z, acc[r][7] + bias1.w);
            float4* op = reinterpret_cast<float4*>(out + (size_t)grow * DIM + tx * 8);
            op[0] = o0;
            op[1] = o1;
        }
    }
}

// ---------------------------------------------------------------------------
// Launch. Inputs resolved BY SIZE (robust to metadata ordering):
//   12,800,000 -> x ; 3,200,000 -> edge_index ; 128 -> b_l ;
//   16,384 (first) -> W_l ; 16,384 (second) -> W_r
// ---------------------------------------------------------------------------
extern "C" void kernel_launch(void* const* d_in, const int* in_sizes, int n_in,
                              void* d_out, int out_size) {
    const float* x  = nullptr;
    const void*  ei = nullptr;
    const float* Wl = nullptr;
    const float* bl = nullptr;
    const float* Wr = nullptr;
    int E = 0;

    for (int i = 0; i < n_in; i++) {
        int s = in_sizes[i];
        if (s == NN * DIM) {
            x = (const float*)d_in[i];
        } else if (s == DIM * DIM) {
            if (!Wl) Wl = (const float*)d_in[i];
            else     Wr = (const float*)d_in[i];
        } else if (s == DIM) {
            bl = (const float*)d_in[i];
        } else {
            ei = d_in[i];
            E  = s / 2;
        }
    }

    float* out = (float*)d_out;
    const int N = NN;

    // 0) detect int32 vs int64 edge buffer
    detect_kernel<<<1, 1>>>((const int*)ei);

    // 1) zero scratch
    zero_kernel<<<1024, 256>>>();

    // 2) edge scatter: one warp per edge, 8 edges per 256-thread block
    int sblocks = (E + 7) / 8;
    scatter_kernel<<<sblocks, 256>>>(x, ei, E);

    // 3) fused normalize + GEMM + bias
    int gblocks = (N + TILE_R - 1) / TILE_R;
    gemm_kernel<<<gblocks, 256>>>(x, Wl, bl, Wr, out, N);
}

// round 7
// speedup vs baseline: 1.4137x; 1.4137x over previous
#include <cuda_runtime.h>
#include <cuda_bf16.h>
#include <mma.h>
#include <cstdint>

using namespace nvcuda;

// Problem constants (shapes fixed by the reference)
#define NN      100000      // nodes
#define DIM     128         // feature dim (in == out)
#define KTOT    256         // combined K: [agg | x]

// Scratch: __device__ globals (no cudaMalloc allowed). 16B-aligned for
// float4 stores / red.global.add.v4.f32 / uint4 loads.
__device__ __align__(16) float g_agg[(size_t)NN * DIM];
__device__ __align__(16) float g_cnt[NN];
__device__ int g_is64;   // 1 if edge_index buffer is int64, 0 if int32
// Combined weight matrix B[256][128] split into bf16 hi/lo:
//   rows 0..127  = W_l (agg path), rows 128..255 = W_r (root path)
__device__ __align__(16) __nv_bfloat16 g_Bhi[KTOT * DIM];
__device__ __align__(16) __nv_bfloat16 g_Blo[KTOT * DIM];

// ---------------------------------------------------------------------------
// Kernel 0: detect edge_index element width (int64 LE -> odd int32 words == 0)
// ---------------------------------------------------------------------------
__global__ void detect_kernel(const int* __restrict__ ei32) {
    int allzero = 1;
#pragma unroll
    for (int i = 1; i < 16; i += 2) allzero &= (ei32[i] == 0);
    g_is64 = allzero;
}

// ---------------------------------------------------------------------------
// Kernel 0b: split weights into bf16 hi/lo pair (hi + lo == fp32 to ~2^-16)
// ---------------------------------------------------------------------------
__global__ void convw_kernel(const float* __restrict__ Wl,
                             const float* __restrict__ Wr) {
    int i = blockIdx.x * blockDim.x + threadIdx.x;
    if (i >= KTOT * DIM) return;
    float f = (i < DIM * DIM) ? Wl[i] : Wr[i - DIM * DIM];
    __nv_bfloat16 hi = __float2bfloat16(f);
    __nv_bfloat16 lo = __float2bfloat16(f - __bfloat162float(hi));
    g_Bhi[i] = hi;
    g_Blo[i] = lo;
}

// ---------------------------------------------------------------------------
// Kernel 1: zero the scratch buffers (float4 stores, grid-stride)
// ---------------------------------------------------------------------------
__global__ void zero_kernel() {
    const size_t n4 = ((size_t)NN * DIM) / 4;
    float4 z = make_float4(0.f, 0.f, 0.f, 0.f);
    float4* a4 = reinterpret_cast<float4*>(g_agg);
    for (size_t i = (size_t)blockIdx.x * blockDim.x + threadIdx.x;
         i < n4; i += (size_t)gridDim.x * blockDim.x) {
        a4[i] = z;
    }
    for (size_t i = (size_t)blockIdx.x * blockDim.x + threadIdx.x;
         i < NN; i += (size_t)gridDim.x * blockDim.x) {
        g_cnt[i] = 0.f;
    }
}

// ---------------------------------------------------------------------------
// Kernel 2: edge scatter. One warp per edge; lane = one float4.
//   red.global.add.v4.f32 quarters the L2 atomic op count vs scalar.
// ---------------------------------------------------------------------------
__global__ void scatter_kernel(const float* __restrict__ x,
                               const void* __restrict__ ei,
                               int E) {
    int gtid = blockIdx.x * blockDim.x + threadIdx.x;
    int e    = gtid >> 5;
    int lane = gtid & 31;
    if (e >= E) return;

    long long src, dst;
    if (g_is64) {
        const long long* e64 = (const long long*)ei;
        src = e64[e];
        dst = e64[(size_t)E + e];
    } else {
        const int* e32 = (const int*)ei;
        src = e32[e];
        dst = e32[(size_t)E + e];
    }
    if ((unsigned long long)src >= NN || (unsigned long long)dst >= NN) return;

    const float4* xs = reinterpret_cast<const float4*>(x + (size_t)src * DIM);
    float4 v = xs[lane];

    float* dp = g_agg + (size_t)dst * DIM + lane * 4;
    asm volatile("red.global.add.v4.f32 [%0], {%1, %2, %3, %4};"
                 :: "l"(dp), "f"(v.x), "f"(v.y), "f"(v.z), "f"(v.w)
                 : "memory");

    if (lane == 0) {
        asm volatile("red.global.add.f32 [%0], %1;"
                     :: "l"(g_cnt + dst), "f"(1.0f)
                     : "memory");
    }
}

// ---------------------------------------------------------------------------
// Kernel 3: tensor-core GEMM with split-bf16 (3-pass) for fp32-class accuracy.
//   out[i,:] = (agg[i,:]/max(cnt,1)) @ W_l + x[i,:] @ W_r + b_l
//   A = [agg_norm | x] (100000 x 256), B = [Wl ; Wr] (256 x 128).
// Block tile 64 x 128, 8 warps of 32x32 (2x2 wmma 16x16 frags).
// K chunked in 16s: chunks 0..7 read agg (scaled), 8..15 read x.
// ---------------------------------------------------------------------------
#define GM      64          // rows per block
#define KC      16          // k chunk
#define ALD     24          // A smem stride (bf16 elems, 48B: mult of 16B)
#define BLD     136         // B smem stride (272B: mult of 16B)
#define OLD     132         // out smem stride (528B: mult of 16B)

__global__ __launch_bounds__(256, 4)
void gemm_kernel(const float* __restrict__ x,
                 const float* __restrict__ bl,
                 float* __restrict__ out,
                 int N) {
    __shared__ union {
        struct {
            __nv_bfloat16 Ahi[GM][ALD];
            __nv_bfloat16 Alo[GM][ALD];
            __nv_bfloat16 Bhi[KC][BLD];
            __nv_bfloat16 Blo[KC][BLD];
        } s;
        float outb[GM][OLD];
    } u;
    __shared__ float inv_sh[GM];

    const int tid  = threadIdx.x;
    const int wid  = tid >> 5;
    const int wm   = wid >> 2;          // 0..1 -> m offset wm*32
    const int wn   = wid & 3;           // 0..3 -> n offset wn*32
    const int row0 = blockIdx.x * GM;

    if (tid < GM) {
        int r = row0 + tid;
        float c = (r < N) ? g_cnt[r] : 1.0f;
        inv_sh[tid] = 1.0f / fmaxf(c, 1.0f);
    }
    __syncthreads();

    wmma::fragment<wmma::accumulator, 16, 16, 16, float> acc[2][2];
#pragma unroll
    for (int mf = 0; mf < 2; mf++)
#pragma unroll
        for (int nf = 0; nf < 2; nf++)
            wmma::fill_fragment(acc[mf][nf], 0.0f);

    // A-load mapping: row = tid/4 (64 rows), 4 floats at col (tid%4)*4
    const int ar = tid >> 2;
    const int ac = (tid & 3) * 4;
    // B-load mapping: 8 bf16 (16B) per thread; idx = tid*8 over 16x128 chunk
    const int br = (tid * 8) >> 7;      // /128
    const int bc = (tid * 8) & 127;

    for (int c = 0; c < KTOT / KC; c++) {
        const bool agg_path = (c < 8);
        const int  kb       = (agg_path ? c : c - 8) * KC;
        const float* Asrc   = agg_path ? g_agg : x;

        // ---- A chunk: fp32 load, scale, split to bf16 hi/lo ----
        {
            int grow = row0 + ar;
            float4 v = make_float4(0.f, 0.f, 0.f, 0.f);
            if (grow < N)
                v = *reinterpret_cast<const float4*>(
                        Asrc + (size_t)grow * DIM + kb + ac);
            if (agg_path) {
                float s = inv_sh[ar];
                v.x *= s; v.y *= s; v.z *= s; v.w *= s;
            }
            const float vv[4] = {v.x, v.y, v.z, v.w};
#pragma unroll
            for (int j = 0; j < 4; j++) {
                __nv_bfloat16 hi = __float2bfloat16(vv[j]);
                __nv_bfloat16 lo = __float2bfloat16(vv[j] - __bfloat162float(hi));
                u.s.Ahi[ar][ac + j] = hi;
                u.s.Alo[ar][ac + j] = lo;
            }
        }
        // ---- B chunk: uint4 copies of pre-split weights ----
        {
            size_t gidx = (size_t)c * KC * DIM + tid * 8;
            *reinterpret_cast<uint4*>(&u.s.Bhi[br][bc]) =
                *reinterpret_cast<const uint4*>(&g_Bhi[gidx]);
            *reinterpret_cast<uint4*>(&u.s.Blo[br][bc]) =
                *reinterpret_cast<const uint4*>(&g_Blo[gidx]);
        }
        __syncthreads();

        // ---- fragments + 3-pass split MMA ----
        wmma::fragment<wmma::matrix_a, 16, 16, 16, __nv_bfloat16, wmma::row_major> fahi[2], falo[2];
        wmma::fragment<wmma::matrix_b, 16, 16, 16, __nv_bfloat16, wmma::row_major> fbhi[2], fblo[2];
#pragma unroll
        for (int mf = 0; mf < 2; mf++) {
            wmma::load_matrix_sync(fahi[mf], &u.s.Ahi[wm * 32 + mf * 16][0], ALD);
            wmma::load_matrix_sync(falo[mf], &u.s.Alo[wm * 32 + mf * 16][0], ALD);
        }
#pragma unroll
        for (int nf = 0; nf < 2; nf++) {
            wmma::load_matrix_sync(fbhi[nf], &u.s.Bhi[0][wn * 32 + nf * 16], BLD);
            wmma::load_matrix_sync(fblo[nf], &u.s.Blo[0][wn * 32 + nf * 16], BLD);
        }
#pragma unroll
        for (int mf = 0; mf < 2; mf++)
#pragma unroll
            for (int nf = 0; nf < 2; nf++) {
                wmma::mma_sync(acc[mf][nf], fahi[mf], fbhi[nf], acc[mf][nf]);
                wmma::mma_sync(acc[mf][nf], fahi[mf], fblo[nf], acc[mf][nf]);
                wmma::mma_sync(acc[mf][nf], falo[mf], fbhi[nf], acc[mf][nf]);
            }
        __syncthreads();
    }

    // ---- epilogue: stage to smem, add bias, store float4s ----
#pragma unroll
    for (int mf = 0; mf < 2; mf++)
#pragma unroll
        for (int nf = 0; nf < 2; nf++)
            wmma::store_matrix_sync(&u.outb[wm * 32 + mf * 16][wn * 32 + nf * 16],
                                    acc[mf][nf], OLD, wmma::mem_row_major);
    __syncthreads();

    {
        int r    = tid >> 2;               // 0..63
        int cb   = (tid & 3) * 32;         // 0,32,64,96
        int grow = row0 + r;
        if (grow < N) {
#pragma unroll
            for (int j = 0; j < 8; j++) {
                int col = cb + j * 4;
                float4 b = *reinterpret_cast<const float4*>(bl + col);
                float4 o;
                o.x = u.outb[r][col + 0] + b.x;
                o.y = u.outb[r][col + 1] + b.y;
                o.z = u.outb[r][col + 2] + b.z;
                o.w = u.outb[r][col + 3] + b.w;
                *reinterpret_cast<float4*>(out + (size_t)grow * DIM + col) = o;
            }
        }
    }
}

// ---------------------------------------------------------------------------
// Launch. Inputs resolved BY SIZE:
//   12,800,000 -> x ; 16,384 (1st) -> W_l ; 128 -> b_l ; 16,384 (2nd) -> W_r ;
//   remaining  -> edge_index (E = size/2)
// ---------------------------------------------------------------------------
extern "C" void kernel_launch(void* const* d_in, const int* in_sizes, int n_in,
                              void* d_out, int out_size) {
    const float* x  = nullptr;
    const void*  ei = nullptr;
    const float* Wl = nullptr;
    const float* bl = nullptr;
    const float* Wr = nullptr;
    int E = 0;

    for (int i = 0; i < n_in; i++) {
        int s = in_sizes[i];
        if (s == NN * DIM) {
            x = (const float*)d_in[i];
        } else if (s == DIM * DIM) {
            if (!Wl) Wl = (const float*)d_in[i];
            else     Wr = (const float*)d_in[i];
        } else if (s == DIM) {
            bl = (const float*)d_in[i];
        } else {
            ei = d_in[i];
            E  = s / 2;
        }
    }

    float* out = (float*)d_out;
    const int N = NN;

    // 0) dtype detect + weight split (independent, tiny)
    detect_kernel<<<1, 1>>>((const int*)ei);
    convw_kernel<<<(KTOT * DIM + 255) / 256, 256>>>(Wl, Wr);

    // 1) zero scratch
    zero_kernel<<<1024, 256>>>();

    // 2) edge scatter: one warp per edge
    int sblocks = (E + 7) / 8;
    scatter_kernel<<<sblocks, 256>>>(x, ei, E);

    // 3) tensor-core GEMM + bias
    int gblocks = (N + GM - 1) / GM;
    gemm_kernel<<<gblocks, 256>>>(x, bl, out, N);
}

// round 8
// speedup vs baseline: 2.1756x; 1.5389x over previous
#include <cuda_runtime.h>
#include <cuda_fp16.h>
#include <cuda_bf16.h>
#include <mma.h>
#include <cstdint>

using namespace nvcuda;

// Problem constants (shapes fixed by the reference)
#define NN      100000      // nodes
#define DIM     128         // feature dim (in == out)
#define KTOT    256         // combined K: [agg | x]
#define EMAX    1600000     // edges (fixed by reference)
#define SBS     1024        // scan block size
#define NB      ((NN + SBS - 1) / SBS)   // 98 scan blocks

// ---------------------------------------------------------------------------
// Scratch (__device__ globals; no cudaMalloc allowed). 16B-aligned where
// accessed via vector ops.
// ---------------------------------------------------------------------------
__device__ __align__(16) float          g_agg[(size_t)NN * DIM];  // mean agg
__device__ __align__(16) __half         g_xh[(size_t)NN * DIM];   // x in fp16
__device__ __align__(16) int            g_csr[EMAX];              // src ids grouped by dst
__device__ int  g_deg[NN];
__device__ int  g_excl[NN];    // exclusive scan within scan-block
__device__ int  g_pos[NN];     // fill cursors (start offsets, mutated)
__device__ int  g_bsum[NB];
__device__ int  g_boff[NB];    // exclusive scan of block sums
__device__ int  g_is64;        // 1 if edge_index buffer is int64, 0 if int32
// Combined weight matrix B[256][128] split into bf16 hi/lo:
//   rows 0..127 = W_l (agg path), rows 128..255 = W_r (root path)
__device__ __align__(16) __nv_bfloat16 g_Bhi[KTOT * DIM];
__device__ __align__(16) __nv_bfloat16 g_Blo[KTOT * DIM];

// ---------------------------------------------------------------------------
// Kernel 0: detect edge_index element width (int64 LE -> odd int32 words == 0)
// ---------------------------------------------------------------------------
__global__ void detect_kernel(const int* __restrict__ ei32) {
    int allzero = 1;
#pragma unroll
    for (int i = 1; i < 16; i += 2) allzero &= (ei32[i] == 0);
    g_is64 = allzero;
}

// ---------------------------------------------------------------------------
// Kernel 0b: split weights into bf16 hi/lo pair (hi + lo == fp32 to ~2^-16)
// ---------------------------------------------------------------------------
__global__ void convw_kernel(const float* __restrict__ Wl,
                             const float* __restrict__ Wr) {
    int i = blockIdx.x * blockDim.x + threadIdx.x;
    if (i >= KTOT * DIM) return;
    float f = (i < DIM * DIM) ? Wl[i] : Wr[i - DIM * DIM];
    __nv_bfloat16 hi = __float2bfloat16(f);
    __nv_bfloat16 lo = __float2bfloat16(f - __bfloat162float(hi));
    g_Bhi[i] = hi;
    g_Blo[i] = lo;
}

// ---------------------------------------------------------------------------
// Kernel 0c: x -> fp16 copy (halves gather traffic; eps 2^-11, well inside
// the 1e-3 budget since accumulation stays fp32).
// ---------------------------------------------------------------------------
__global__ void convx_kernel(const float* __restrict__ x) {
    size_t i = (size_t)blockIdx.x * blockDim.x + threadIdx.x;   // float4 units
    const size_t n4 = (size_t)NN * DIM / 4;
    if (i >= n4) return;
    float4 v = reinterpret_cast<const float4*>(x)[i];
    __half2 h0 = __floats2half2_rn(v.x, v.y);
    __half2 h1 = __floats2half2_rn(v.z, v.w);
    uint2 u;
    u.x = *reinterpret_cast<unsigned*>(&h0);
    u.y = *reinterpret_cast<unsigned*>(&h1);
    reinterpret_cast<uint2*>(g_xh)[i] = u;
}

// ---------------------------------------------------------------------------
// CSR build: degree count -> block scan -> block-sum scan -> cursors -> fill
// ---------------------------------------------------------------------------
__global__ void zerodeg_kernel() {
    int i = blockIdx.x * blockDim.x + threadIdx.x;
    if (i < NN) g_deg[i] = 0;
}

__global__ void count_kernel(const void* __restrict__ ei, int E) {
    int e = blockIdx.x * blockDim.x + threadIdx.x;
    if (e >= E) return;
    int dst = g_is64 ? (int)((const long long*)ei)[(size_t)E + e]
                     : ((const int*)ei)[(size_t)E + e];
    if ((unsigned)dst < NN) atomicAdd(&g_deg[dst], 1);
}

__global__ void scan1_kernel() {
    __shared__ int sh[SBS];
    int t = threadIdx.x;
    int i = blockIdx.x * SBS + t;
    int v = (i < NN) ? g_deg[i] : 0;
    sh[t] = v;
    __syncthreads();
    for (int off = 1; off < SBS; off <<= 1) {
        int u = (t >= off) ? sh[t - off] : 0;
        __syncthreads();
        sh[t] += u;
        __syncthreads();
    }
    if (i < NN) g_excl[i] = sh[t] - v;
    if (t == SBS - 1) g_bsum[blockIdx.x] = sh[t];
}

__global__ void scan2_kernel() {
    __shared__ int sh[NB];
    int t = threadIdx.x;
    if (t < NB) sh[t] = g_bsum[t];
    __syncthreads();
    if (t == 0) {
        int acc = 0;
        for (int i = 0; i < NB; i++) { int v = sh[i]; sh[i] = acc; acc += v; }
    }
    __syncthreads();
    if (t < NB) g_boff[t] = sh[t];
}

__global__ void cursor_kernel() {
    int i = blockIdx.x * blockDim.x + threadIdx.x;
    if (i < NN) g_pos[i] = g_excl[i] + g_boff[i >> 10];
}

__global__ void fill_kernel(const void* __restrict__ ei, int E) {
    int e = blockIdx.x * blockDim.x + threadIdx.x;
    if (e >= E) return;
    int src, dst;
    if (g_is64) {
        const long long* e64 = (const long long*)ei;
        src = (int)e64[e];
        dst = (int)e64[(size_t)E + e];
    } else {
        const int* e32 = (const int*)ei;
        src = e32[e];
        dst = e32[(size_t)E + e];
    }
    if ((unsigned)src >= NN || (unsigned)dst >= NN) return;
    int slot = atomicAdd(&g_pos[dst], 1);
    g_csr[slot] = src;
}

// ---------------------------------------------------------------------------
// Gather-aggregate: one warp per node. Cooperative src-id read + shfl
// broadcast; each lane accumulates 4 features (uint2 = 4 fp16) in fp32
// registers; single float4 store of the normalized mean. Zero FP atomics.
// ---------------------------------------------------------------------------
__global__ __launch_bounds__(256)
void gather_kernel(int N) {
    int node = (blockIdx.x * blockDim.x + threadIdx.x) >> 5;
    int lane = threadIdx.x & 31;
    if (node >= N) return;

    int start = g_excl[node] + g_boff[node >> 10];
    int deg   = g_deg[node];

    float a0 = 0.f, a1 = 0.f, a2 = 0.f, a3 = 0.f;
    for (int base = 0; base < deg; base += 32) {
        int m = min(32, deg - base);
        int s = (lane < m) ? g_csr[start + base + lane] : 0;
#pragma unroll 4
        for (int e = 0; e < m; e++) {
            int src = __shfl_sync(0xffffffffu, s, e);
            uint2 v = *reinterpret_cast<const uint2*>(
                          g_xh + (size_t)src * DIM + lane * 4);
            __half2 h0 = *reinterpret_cast<__half2*>(&v.x);
            __half2 h1 = *reinterpret_cast<__half2*>(&v.y);
            float2 f0 = __half22float2(h0);
            float2 f1 = __half22float2(h1);
            a0 += f0.x; a1 += f0.y; a2 += f1.x; a3 += f1.y;
        }
    }
    float inv = 1.0f / fmaxf((float)deg, 1.0f);
    float4 o  = make_float4(a0 * inv, a1 * inv, a2 * inv, a3 * inv);
    *reinterpret_cast<float4*>(g_agg + (size_t)node * DIM + lane * 4) = o;
}

// ---------------------------------------------------------------------------
// Tensor-core GEMM with split-bf16 (3-pass) for fp32-class accuracy.
//   out[i,:] = agg[i,:] @ W_l + x[i,:] @ W_r + b_l   (agg already the mean)
// Block tile 64 x 128, 8 warps of 32x32 (2x2 wmma 16x16 frags), K chunk 16.
// ---------------------------------------------------------------------------
#define GM      64          // rows per block
#define KC      16          // k chunk
#define ALD     24          // A smem stride (bf16): 48B, mult of 16B
#define BLD     136         // B smem stride (bf16): 272B, mult of 16B
#define OLD     132         // out smem stride (f32): 528B, mult of 16B

__global__ __launch_bounds__(256, 4)
void gemm_kernel(const float* __restrict__ x,
                 const float* __restrict__ bl,
                 float* __restrict__ out,
                 int N) {
    __shared__ union {
        struct {
            __nv_bfloat16 Ahi[GM][ALD];
            __nv_bfloat16 Alo[GM][ALD];
            __nv_bfloat16 Bhi[KC][BLD];
            __nv_bfloat16 Blo[KC][BLD];
        } s;
        float outb[GM][OLD];
    } u;

    const int tid  = threadIdx.x;
    const int wid  = tid >> 5;
    const int wm   = wid >> 2;          // 0..1 -> m offset wm*32
    const int wn   = wid & 3;           // 0..3 -> n offset wn*32
    const int row0 = blockIdx.x * GM;

    wmma::fragment<wmma::accumulator, 16, 16, 16, float> acc[2][2];
#pragma unroll
    for (int mf = 0; mf < 2; mf++)
#pragma unroll
        for (int nf = 0; nf < 2; nf++)
            wmma::fill_fragment(acc[mf][nf], 0.0f);

    // A-load mapping: row = tid/4 (64 rows), 4 floats at col (tid%4)*4
    const int ar = tid >> 2;
    const int ac = (tid & 3) * 4;
    // B-load mapping: 8 bf16 (16B) per thread over the 16x128 chunk
    const int br = (tid * 8) >> 7;
    const int bc = (tid * 8) & 127;

    for (int c = 0; c < KTOT / KC; c++) {
        const bool agg_path = (c < 8);
        const int  kb       = (agg_path ? c : c - 8) * KC;
        const float* Asrc   = agg_path ? g_agg : x;

        // ---- A chunk: fp32 load, split to bf16 hi/lo ----
        {
            int grow = row0 + ar;
            float4 v = make_float4(0.f, 0.f, 0.f, 0.f);
            if (grow < N)
                v = *reinterpret_cast<const float4*>(
                        Asrc + (size_t)grow * DIM + kb + ac);
            const float vv[4] = {v.x, v.y, v.z, v.w};
#pragma unroll
            for (int j = 0; j < 4; j++) {
                __nv_bfloat16 hi = __float2bfloat16(vv[j]);
                __nv_bfloat16 lo = __float2bfloat16(vv[j] - __bfloat162float(hi));
                u.s.Ahi[ar][ac + j] = hi;
                u.s.Alo[ar][ac + j] = lo;
            }
        }
        // ---- B chunk: uint4 copies of pre-split weights ----
        {
            size_t gidx = (size_t)c * KC * DIM + tid * 8;
            *reinterpret_cast<uint4*>(&u.s.Bhi[br][bc]) =
                *reinterpret_cast<const uint4*>(&g_Bhi[gidx]);
            *reinterpret_cast<uint4*>(&u.s.Blo[br][bc]) =
                *reinterpret_cast<const uint4*>(&g_Blo[gidx]);
        }
        __syncthreads();

        // ---- fragments + 3-pass split MMA (hi*hi + hi*lo + lo*hi) ----
        wmma::fragment<wmma::matrix_a, 16, 16, 16, __nv_bfloat16, wmma::row_major> fahi[2], falo[2];
        wmma::fragment<wmma::matrix_b, 16, 16, 16, __nv_bfloat16, wmma::row_major> fbhi[2], fblo[2];
#pragma unroll
        for (int mf = 0; mf < 2; mf++) {
            wmma::load_matrix_sync(fahi[mf], &u.s.Ahi[wm * 32 + mf * 16][0], ALD);
            wmma::load_matrix_sync(falo[mf], &u.s.Alo[wm * 32 + mf * 16][0], ALD);
        }
#pragma unroll
        for (int nf = 0; nf < 2; nf++) {
            wmma::load_matrix_sync(fbhi[nf], &u.s.Bhi[0][wn * 32 + nf * 16], BLD);
            wmma::load_matrix_sync(fblo[nf], &u.s.Blo[0][wn * 32 + nf * 16], BLD);
        }
#pragma unroll
        for (int mf = 0; mf < 2; mf++)
#pragma unroll
            for (int nf = 0; nf < 2; nf++) {
                wmma::mma_sync(acc[mf][nf], fahi[mf], fbhi[nf], acc[mf][nf]);
                wmma::mma_sync(acc[mf][nf], fahi[mf], fblo[nf], acc[mf][nf]);
                wmma::mma_sync(acc[mf][nf], falo[mf], fbhi[nf], acc[mf][nf]);
            }
        __syncthreads();
    }

    // ---- epilogue: stage to smem, add bias, store float4s ----
#pragma unroll
    for (int mf = 0; mf < 2; mf++)
#pragma unroll
        for (int nf = 0; nf < 2; nf++)
            wmma::store_matrix_sync(&u.outb[wm * 32 + mf * 16][wn * 32 + nf * 16],
                                    acc[mf][nf], OLD, wmma::mem_row_major);
    __syncthreads();

    {
        int r    = tid >> 2;               // 0..63
        int cb   = (tid & 3) * 32;         // 0,32,64,96
        int grow = row0 + r;
        if (grow < N) {
#pragma unroll
            for (int j = 0; j < 8; j++) {
                int col = cb + j * 4;
                float4 b = *reinterpret_cast<const float4*>(bl + col);
                float4 o;
                o.x = u.outb[r][col + 0] + b.x;
                o.y = u.outb[r][col + 1] + b.y;
                o.z = u.outb[r][col + 2] + b.z;
                o.w = u.outb[r][col + 3] + b.w;
                *reinterpret_cast<float4*>(out + (size_t)grow * DIM + col) = o;
            }
        }
    }
}

// ---------------------------------------------------------------------------
// Launch. Inputs resolved BY SIZE:
//   12,800,000 -> x ; 16,384 (1st) -> W_l ; 128 -> b_l ; 16,384 (2nd) -> W_r ;
//   remaining  -> edge_index (E = size/2)
// ---------------------------------------------------------------------------
extern "C" void kernel_launch(void* const* d_in, const int* in_sizes, int n_in,
                              void* d_out, int out_size) {
    const float* x  = nullptr;
    const void*  ei = nullptr;
    const float* Wl = nullptr;
    const float* bl = nullptr;
    const float* Wr = nullptr;
    int E = 0;

    for (int i = 0; i < n_in; i++) {
        int s = in_sizes[i];
        if (s == NN * DIM) {
            x = (const float*)d_in[i];
        } else if (s == DIM * DIM) {
            if (!Wl) Wl = (const float*)d_in[i];
            else     Wr = (const float*)d_in[i];
        } else if (s == DIM) {
            bl = (const float*)d_in[i];
        } else {
            ei = d_in[i];
            E  = s / 2;
        }
    }
    if (E > EMAX) E = EMAX;   // scratch bound (problem fixes E = 1.6M)

    float* out = (float*)d_out;
    const int N = NN;

    // 0) dtype detect (must precede edge readers) + conversions
    detect_kernel<<<1, 1>>>((const int*)ei);
    convw_kernel<<<(KTOT * DIM + 255) / 256, 256>>>(Wl, Wr);
    convx_kernel<<<(NN * DIM / 4 + 255) / 256, 256>>>(x);

    // 1) CSR build
    zerodeg_kernel<<<(NN + 255) / 256, 256>>>();
    count_kernel<<<(E + 255) / 256, 256>>>(ei, E);
    scan1_kernel<<<NB, SBS>>>();
    scan2_kernel<<<1, 128>>>();
    cursor_kernel<<<(NN + 255) / 256, 256>>>();
    fill_kernel<<<(E + 255) / 256, 256>>>(ei, E);

    // 2) gather-aggregate (warp per node)
    gather_kernel<<<(N * 32 + 255) / 256, 256>>>(N);

    // 3) tensor-core GEMM + bias
    gemm_kernel<<<(N + GM - 1) / GM, 256>>>(x, bl, out, N);
}

// round 9
// speedup vs baseline: 2.2162x; 1.0187x over previous
#include <cuda_runtime.h>
#include <cuda_fp16.h>
#include <cuda_bf16.h>
#include <mma.h>
#include <cstdint>

using namespace nvcuda;

// Problem constants (shapes fixed by the reference)
#define NN      100000      // nodes
#define DIM     128         // feature dim (in == out)
#define KTOT    256         // combined K: [agg | x]
#define EMAX    1600000     // edges (fixed by reference)
#define SBS     1024        // scan block size
#define NB      ((NN + SBS - 1) / SBS)   // 98 scan blocks

// ---------------------------------------------------------------------------
// Scratch (__device__ globals; no cudaMalloc allowed).
// ---------------------------------------------------------------------------
__device__ __align__(16) __half g_xh[(size_t)NN * DIM];   // x fp16 hi (gather + gemm)
__device__ __align__(16) __half g_xl[(size_t)NN * DIM];   // x fp16 lo (gemm)
__device__ __align__(16) __half g_ah[(size_t)NN * DIM];   // agg fp16 hi
__device__ __align__(16) __half g_al[(size_t)NN * DIM];   // agg fp16 lo
__device__ __align__(16) int    g_csr[EMAX];              // src ids grouped by dst
__device__ int  g_deg[NN];
__device__ int  g_excl[NN];    // exclusive scan within scan-block
__device__ int  g_pos[NN];     // fill cursors
__device__ int  g_bsum[NB];
__device__ int  g_boff[NB];    // exclusive scan of block sums
__device__ int  g_is64;        // 1 if edge_index is int64, 0 if int32
// Combined weight B[256][128] fp16 hi/lo: rows 0..127 = W_l, 128..255 = W_r
__device__ __align__(16) __half g_Bh[KTOT * DIM];
__device__ __align__(16) __half g_Bl[KTOT * DIM];

// ---------------------------------------------------------------------------
// cp.async helper: 16B global->shared, src-size sz (0 => zero-fill)
// ---------------------------------------------------------------------------
__device__ __forceinline__ void cpa16(void* s, const void* g, int sz) {
    uint32_t sa = (uint32_t)__cvta_generic_to_shared(s);
    asm volatile("cp.async.ca.shared.global [%0], [%1], 16, %2;\n"
                 :: "r"(sa), "l"(g), "r"(sz));
}
__device__ __forceinline__ void cpa_wait() {
    asm volatile("cp.async.commit_group;\n");
    asm volatile("cp.async.wait_group 0;\n");
}

// ---------------------------------------------------------------------------
// Kernel 0: zero degrees + detect edge width (merged to save a launch)
// ---------------------------------------------------------------------------
__global__ void detect_zero_kernel(const int* __restrict__ ei32) {
    int i = blockIdx.x * blockDim.x + threadIdx.x;
    if (i < NN) g_deg[i] = 0;
    if (i == 0) {
        int allzero = 1;
#pragma unroll
        for (int j = 1; j < 16; j += 2) allzero &= (ei32[j] == 0);
        g_is64 = allzero;
    }
}

// ---------------------------------------------------------------------------
// Kernel 0b: weights -> fp16 hi/lo (hi + lo carries ~22 mantissa bits)
// ---------------------------------------------------------------------------
__global__ void convw_kernel(const float* __restrict__ Wl,
                             const float* __restrict__ Wr) {
    int i = blockIdx.x * blockDim.x + threadIdx.x;
    if (i >= KTOT * DIM) return;
    float f = (i < DIM * DIM) ? Wl[i] : Wr[i - DIM * DIM];
    __half hi = __float2half_rn(f);
    __half lo = __float2half_rn(f - __half2float(hi));
    g_Bh[i] = hi;
    g_Bl[i] = lo;
}

// ---------------------------------------------------------------------------
// Kernel 0c: x -> fp16 hi/lo planes
// ---------------------------------------------------------------------------
__global__ void convx_kernel(const float* __restrict__ x) {
    size_t i = (size_t)blockIdx.x * blockDim.x + threadIdx.x;   // float4 units
    const size_t n4 = (size_t)NN * DIM / 4;
    if (i >= n4) return;
    float4 v = reinterpret_cast<const float4*>(x)[i];
    __half h0 = __float2half_rn(v.x), h1 = __float2half_rn(v.y);
    __half h2 = __float2half_rn(v.z), h3 = __float2half_rn(v.w);
    __half l0 = __float2half_rn(v.x - __half2float(h0));
    __half l1 = __float2half_rn(v.y - __half2float(h1));
    __half l2 = __float2half_rn(v.z - __half2float(h2));
    __half l3 = __float2half_rn(v.w - __half2float(h3));
    __half2 hh0 = __halves2half2(h0, h1), hh1 = __halves2half2(h2, h3);
    __half2 ll0 = __halves2half2(l0, l1), ll1 = __halves2half2(l2, l3);
    uint2 uh, ul;
    uh.x = *reinterpret_cast<unsigned*>(&hh0);
    uh.y = *reinterpret_cast<unsigned*>(&hh1);
    ul.x = *reinterpret_cast<unsigned*>(&ll0);
    ul.y = *reinterpret_cast<unsigned*>(&ll1);
    reinterpret_cast<uint2*>(g_xh)[i] = uh;
    reinterpret_cast<uint2*>(g_xl)[i] = ul;
}

// ---------------------------------------------------------------------------
// CSR build: degree count -> block scan -> block-sum scan -> cursors -> fill
// ---------------------------------------------------------------------------
__global__ void count_kernel(const void* __restrict__ ei, int E) {
    int e = blockIdx.x * blockDim.x + threadIdx.x;
    if (e >= E) return;
    int dst = g_is64 ? (int)((const long long*)ei)[(size_t)E + e]
                     : ((const int*)ei)[(size_t)E + e];
    if ((unsigned)dst < NN) atomicAdd(&g_deg[dst], 1);
}

__global__ void scan1_kernel() {
    __shared__ int sh[SBS];
    int t = threadIdx.x;
    int i = blockIdx.x * SBS + t;
    int v = (i < NN) ? g_deg[i] : 0;
    sh[t] = v;
    __syncthreads();
    for (int off = 1; off < SBS; off <<= 1) {
        int u = (t >= off) ? sh[t - off] : 0;
        __syncthreads();
        sh[t] += u;
        __syncthreads();
    }
    if (i < NN) g_excl[i] = sh[t] - v;
    if (t == SBS - 1) g_bsum[blockIdx.x] = sh[t];
}

__global__ void scan2_kernel() {
    __shared__ int sh[NB];
    int t = threadIdx.x;
    if (t < NB) sh[t] = g_bsum[t];
    __syncthreads();
    if (t == 0) {
        int acc = 0;
        for (int i = 0; i < NB; i++) { int v = sh[i]; sh[i] = acc; acc += v; }
    }
    __syncthreads();
    if (t < NB) g_boff[t] = sh[t];
}

__global__ void cursor_kernel() {
    int i = blockIdx.x * blockDim.x + threadIdx.x;
    if (i < NN) g_pos[i] = g_excl[i] + g_boff[i >> 10];
}

__global__ void fill_kernel(const void* __restrict__ ei, int E) {
    int e = blockIdx.x * blockDim.x + threadIdx.x;
    if (e >= E) return;
    int src, dst;
    if (g_is64) {
        const long long* e64 = (const long long*)ei;
        src = (int)e64[e];
        dst = (int)e64[(size_t)E + e];
    } else {
        const int* e32 = (const int*)ei;
        src = e32[e];
        dst = e32[(size_t)E + e];
    }
    if ((unsigned)src >= NN || (unsigned)dst >= NN) return;
    int slot = atomicAdd(&g_pos[dst], 1);
    g_csr[slot] = src;
}

// ---------------------------------------------------------------------------
// Gather-aggregate: one warp per node. fp32 accumulation of fp16 features;
// writes the mean directly as fp16 hi/lo planes (ready for tensor-core GEMM).
// ---------------------------------------------------------------------------
__global__ __launch_bounds__(256)
void gather_kernel(int N) {
    int node = (blockIdx.x * blockDim.x + threadIdx.x) >> 5;
    int lane = threadIdx.x & 31;
    if (node >= N) return;

    int start = g_excl[node] + g_boff[node >> 10];
    int deg   = g_deg[node];

    float a0 = 0.f, a1 = 0.f, a2 = 0.f, a3 = 0.f;
    for (int base = 0; base < deg; base += 32) {
        int m = min(32, deg - base);
        int s = (lane < m) ? g_csr[start + base + lane] : 0;
#pragma unroll 4
        for (int e = 0; e < m; e++) {
            int src = __shfl_sync(0xffffffffu, s, e);
            uint2 v = *reinterpret_cast<const uint2*>(
                          g_xh + (size_t)src * DIM + lane * 4);
            __half2 h0 = *reinterpret_cast<__half2*>(&v.x);
            __half2 h1 = *reinterpret_cast<__half2*>(&v.y);
            float2 f0 = __half22float2(h0);
            float2 f1 = __half22float2(h1);
            a0 += f0.x; a1 += f0.y; a2 += f1.x; a3 += f1.y;
        }
    }
    float inv = 1.0f / fmaxf((float)deg, 1.0f);
    float m0 = a0 * inv, m1 = a1 * inv, m2 = a2 * inv, m3 = a3 * inv;

    __half h0 = __float2half_rn(m0), h1 = __float2half_rn(m1);
    __half h2 = __float2half_rn(m2), h3 = __float2half_rn(m3);
    __half l0 = __float2half_rn(m0 - __half2float(h0));
    __half l1 = __float2half_rn(m1 - __half2float(h1));
    __half l2 = __float2half_rn(m2 - __half2float(h2));
    __half l3 = __float2half_rn(m3 - __half2float(h3));
    __half2 hh0 = __halves2half2(h0, h1), hh1 = __halves2half2(h2, h3);
    __half2 ll0 = __halves2half2(l0, l1), ll1 = __halves2half2(l2, l3);
    uint2 uh, ul;
    uh.x = *reinterpret_cast<unsigned*>(&hh0);
    uh.y = *reinterpret_cast<unsigned*>(&hh1);
    ul.x = *reinterpret_cast<unsigned*>(&ll0);
    ul.y = *reinterpret_cast<unsigned*>(&ll1);
    size_t off = ((size_t)node * DIM + lane * 4) / 4;
    reinterpret_cast<uint2*>(g_ah)[off] = uh;
    reinterpret_cast<uint2*>(g_al)[off] = ul;
}

// ---------------------------------------------------------------------------
// Tensor-core GEMM, fp16 hi/lo 3-pass (hi*hi + hi*lo + lo*hi ~ fp32 exact).
//   out[i,:] = agg[i,:] @ W_l + x[i,:] @ W_r + b_l
// All operands pre-split: tiles are pure 16B cp.async copies. KC=32 -> 8 iters.
// Block tile 64 x 128, 8 warps of 32x32 (2x2 wmma 16x16 frags).
// ---------------------------------------------------------------------------
#define GM      64          // rows per block
#define KC      32          // k chunk
#define ALD     40          // A smem stride (halves): 80B = 5*16B
#define BLD     136         // B smem stride (halves): 272B = 17*16B
#define OLD     132         // out smem stride (f32): 528B

__global__ __launch_bounds__(256, 4)
void gemm_kernel(const float* __restrict__ bl,
                 float* __restrict__ out,
                 int N) {
    __shared__ union {
        struct {
            __half Ahi[GM][ALD];
            __half Alo[GM][ALD];
            __half Bhi[KC][BLD];
            __half Blo[KC][BLD];
        } s;
        float outb[GM][OLD];
    } u;

    const int tid  = threadIdx.x;
    const int wid  = tid >> 5;
    const int wm   = wid >> 2;          // 0..1 -> m offset wm*32
    const int wn   = wid & 3;           // 0..3 -> n offset wn*32
    const int row0 = blockIdx.x * GM;

    wmma::fragment<wmma::accumulator, 16, 16, 16, float> acc[2][2];
#pragma unroll
    for (int mf = 0; mf < 2; mf++)
#pragma unroll
        for (int nf = 0; nf < 2; nf++)
            wmma::fill_fragment(acc[mf][nf], 0.0f);

    // A-load mapping: 64x32 halves = 4KB/plane; 16B (8 halves) per thread
    const int ar = tid >> 2;            // row 0..63
    const int ac = (tid & 3) * 8;       // col 0,8,16,24
    // B-load mapping: 32x128 halves = 8KB/plane; 16B per thread
    const int br = tid >> 4;            // row 0..15  (x2 halves of chunk)
    const int bc = (tid & 15) * 8;      // col 0..120

    for (int c = 0; c < KTOT / KC; c++) {
        const bool agg_path = (c < 4);
        const int  kb       = (agg_path ? c : c - 4) * KC;
        const __half* Ah    = agg_path ? g_ah : g_xh;
        const __half* Al    = agg_path ? g_al : g_xl;

        // ---- A tiles (zero-fill rows past N via src-size 0) ----
        {
            int grow = row0 + ar;
            int sz   = (grow < N) ? 16 : 0;
            int arow = (grow < N) ? grow : 0;
            const __half* gh = Ah + (size_t)arow * DIM + kb + ac;
            const __half* gl = Al + (size_t)arow * DIM + kb + ac;
            cpa16(&u.s.Ahi[ar][ac], gh, sz);
            cpa16(&u.s.Alo[ar][ac], gl, sz);
        }
        // ---- B tiles (two 16-row halves per thread: 32 rows total) ----
        {
            size_t g0 = (size_t)(c * KC + br) * DIM + bc;
            size_t g1 = (size_t)(c * KC + br + 16) * DIM + bc;
            cpa16(&u.s.Bhi[br][bc],      g_Bh + g0, 16);
            cpa16(&u.s.Bhi[br + 16][bc], g_Bh + g1, 16);
            cpa16(&u.s.Blo[br][bc],      g_Bl + g0, 16);
            cpa16(&u.s.Blo[br + 16][bc], g_Bl + g1, 16);
        }
        cpa_wait();
        __syncthreads();

        // ---- 3-pass split MMA over the two 16-k steps ----
#pragma unroll
        for (int ks = 0; ks < KC; ks += 16) {
            wmma::fragment<wmma::matrix_a, 16, 16, 16, __half, wmma::row_major> fahi[2], falo[2];
            wmma::fragment<wmma::matrix_b, 16, 16, 16, __half, wmma::row_major> fbhi[2], fblo[2];
#pragma unroll
            for (int mf = 0; mf < 2; mf++) {
                wmma::load_matrix_sync(fahi[mf], &u.s.Ahi[wm * 32 + mf * 16][ks], ALD);
                wmma::load_matrix_sync(falo[mf], &u.s.Alo[wm * 32 + mf * 16][ks], ALD);
            }
#pragma unroll
            for (int nf = 0; nf < 2; nf++) {
                wmma::load_matrix_sync(fbhi[nf], &u.s.Bhi[ks][wn * 32 + nf * 16], BLD);
                wmma::load_matrix_sync(fblo[nf], &u.s.Blo[ks][wn * 32 + nf * 16], BLD);
            }
#pragma unroll
            for (int mf = 0; mf < 2; mf++)
#pragma unroll
                for (int nf = 0; nf < 2; nf++) {
                    wmma::mma_sync(acc[mf][nf], fahi[mf], fbhi[nf], acc[mf][nf]);
                    wmma::mma_sync(acc[mf][nf], fahi[mf], fblo[nf], acc[mf][nf]);
                    wmma::mma_sync(acc[mf][nf], falo[mf], fbhi[nf], acc[mf][nf]);
                }
        }
        __syncthreads();
    }

    // ---- epilogue: stage to smem, add bias, store float4s ----
#pragma unroll
    for (int mf = 0; mf < 2; mf++)
#pragma unroll
        for (int nf = 0; nf < 2; nf++)
            wmma::store_matrix_sync(&u.outb[wm * 32 + mf * 16][wn * 32 + nf * 16],
                                    acc[mf][nf], OLD, wmma::mem_row_major);
    __syncthreads();

    {
        int r    = tid >> 2;               // 0..63
        int cb   = (tid & 3) * 32;         // 0,32,64,96
        int grow = row0 + r;
        if (grow < N) {
#pragma unroll
            for (int j = 0; j < 8; j++) {
                int col = cb + j * 4;
                float4 b = *reinterpret_cast<const float4*>(bl + col);
                float4 o;
                o.x = u.outb[r][col + 0] + b.x;
                o.y = u.outb[r][col + 1] + b.y;
                o.z = u.outb[r][col + 2] + b.z;
                o.w = u.outb[r][col + 3] + b.w;
                *reinterpret_cast<float4*>(out + (size_t)grow * DIM + col) = o;
            }
        }
    }
}

// ---------------------------------------------------------------------------
// Launch. Inputs resolved BY SIZE:
//   12,800,000 -> x ; 16,384 (1st) -> W_l ; 128 -> b_l ; 16,384 (2nd) -> W_r ;
//   remaining  -> edge_index (E = size/2)
// ---------------------------------------------------------------------------
extern "C" void kernel_launch(void* const* d_in, const int* in_sizes, int n_in,
                              void* d_out, int out_size) {
    const float* x  = nullptr;
    const void*  ei = nullptr;
    const float* Wl = nullptr;
    const float* bl = nullptr;
    const float* Wr = nullptr;
    int E = 0;

    for (int i = 0; i < n_in; i++) {
        int s = in_sizes[i];
        if (s == NN * DIM) {
            x = (const float*)d_in[i];
        } else if (s == DIM * DIM) {
            if (!Wl) Wl = (const float*)d_in[i];
            else     Wr = (const float*)d_in[i];
        } else if (s == DIM) {
            bl = (const float*)d_in[i];
        } else {
            ei = d_in[i];
            E  = s / 2;
        }
    }
    if (E > EMAX) E = EMAX;

    float* out = (float*)d_out;
    const int N = NN;

    // 0) detect+zero, conversions
    detect_zero_kernel<<<(NN + 255) / 256, 256>>>((const int*)ei);
    convw_kernel<<<(KTOT * DIM + 255) / 256, 256>>>(Wl, Wr);
    convx_kernel<<<(NN * DIM / 4 + 255) / 256, 256>>>(x);

    // 1) CSR build
    count_kernel<<<(E + 255) / 256, 256>>>(ei, E);
    scan1_kernel<<<NB, SBS>>>();
    scan2_kernel<<<1, 128>>>();
    cursor_kernel<<<(NN + 255) / 256, 256>>>();
    fill_kernel<<<(E + 255) / 256, 256>>>(ei, E);

    // 2) gather-aggregate (warp per node)
    gather_kernel<<<(N * 32 + 255) / 256, 256>>>(N);

    // 3) tensor-core GEMM + bias
    gemm_kernel<<<(N + GM - 1) / GM, 256>>>(bl, out, N);
}